// round 6
// baseline (speedup 1.0000x reference)
#include <cuda_runtime.h>
#include <cuda_bf16.h>

#define B_     8
#define N_     2048
#define FIN    128
#define FOUT   64
#define ALPHA  0.2f
#define JSPLIT 2

// Scratch (device globals — no allocation allowed)
__device__ float g_Wh[B_ * N_ * FOUT];            // 4 MB
__device__ float g_f[B_ * N_];
__device__ float g_g[B_ * N_];
__device__ float g_pacc[JSPLIT][B_ * N_ * FOUT];  // 8 MB partial accumulators
__device__ float g_psum[JSPLIT][B_ * N_];         // partial rowsums

// ---------------------------------------------------------------------------
// packed fp32x2 helpers (sm_100+ PTX; ptxas never emits FFMA2 from C++)
// ---------------------------------------------------------------------------
__device__ __forceinline__ unsigned long long fma2(unsigned long long a,
                                                   unsigned long long b,
                                                   unsigned long long c) {
    unsigned long long d;
    asm("fma.rn.f32x2 %0, %1, %2, %3;" : "=l"(d) : "l"(a), "l"(b), "l"(c));
    return d;
}
__device__ __forceinline__ unsigned long long pack2(float p) {
    unsigned long long d;
    asm("mov.b64 %0, {%1, %1};" : "=l"(d) : "r"(__float_as_uint(p)));
    return d;
}
__device__ __forceinline__ unsigned smem_u32(const void* p) {
    return (unsigned)__cvta_generic_to_shared(p);
}
#define CP16(dst, src) \
    asm volatile("cp.async.cg.shared.global [%0], [%1], 16;" :: "r"(dst), "l"(src))

// ---------------------------------------------------------------------------
// Kernel 1: Wh = h @ W ; f = Wh @ a1 ; g = Wh @ a2
// ---------------------------------------------------------------------------
__global__ void __launch_bounds__(256) k_wh(const float* __restrict__ h,
                                            const float* __restrict__ W,
                                            const float* __restrict__ a) {
    __shared__ __align__(16) float W_t[FOUT][FIN + 4];
    __shared__ __align__(16) float h_s[16][FIN];
    __shared__ float red[16][2][2];

    int row0 = blockIdx.x * 16;
    int tid  = threadIdx.x;
    int fc   = tid & 63;
    int rg   = tid >> 6;

    #pragma unroll 8
    for (int l = 0; l < 32; l++) {
        int idx = tid + l * 256;
        int k = idx >> 6, c = idx & 63;
        W_t[c][k] = W[k * FOUT + c];
    }
    #pragma unroll
    for (int l = 0; l < 8; l++) {
        int idx = tid + l * 256;
        int r = idx >> 7, k = idx & 127;
        h_s[r][k] = h[(size_t)(row0 + r) * FIN + k];
    }
    __syncthreads();

    float acc[4] = {0.f, 0.f, 0.f, 0.f};
    #pragma unroll 4
    for (int k4 = 0; k4 < FIN; k4 += 4) {
        float4 w = *(const float4*)&W_t[fc][k4];
        #pragma unroll
        for (int r = 0; r < 4; r++) {
            float4 hv = *(const float4*)&h_s[rg * 4 + r][k4];
            acc[r] = fmaf(hv.x, w.x, acc[r]);
            acc[r] = fmaf(hv.y, w.y, acc[r]);
            acc[r] = fmaf(hv.z, w.z, acc[r]);
            acc[r] = fmaf(hv.w, w.w, acc[r]);
        }
    }

    float a1 = a[fc], a2 = a[FOUT + fc];
    float pf[4], pg[4];
    #pragma unroll
    for (int r = 0; r < 4; r++) {
        g_Wh[(size_t)(row0 + rg * 4 + r) * FOUT + fc] = acc[r];
        pf[r] = acc[r] * a1;
        pg[r] = acc[r] * a2;
    }
    #pragma unroll
    for (int off = 16; off > 0; off >>= 1) {
        #pragma unroll
        for (int r = 0; r < 4; r++) {
            pf[r] += __shfl_down_sync(0xffffffffu, pf[r], off);
            pg[r] += __shfl_down_sync(0xffffffffu, pg[r], off);
        }
    }
    int hb = (tid >> 5) & 1;
    if ((tid & 31) == 0) {
        #pragma unroll
        for (int r = 0; r < 4; r++) {
            red[rg * 4 + r][hb][0] = pf[r];
            red[rg * 4 + r][hb][1] = pg[r];
        }
    }
    __syncthreads();
    if (tid < 16) {
        g_f[row0 + tid] = red[tid][0][0] + red[tid][1][0];
        g_g[row0 + tid] = red[tid][0][1] + red[tid][1][1];
    }
}

// ---------------------------------------------------------------------------
// Kernel 2: fused masked-softmax attention + att@Wh, j-split into JSPLIT
// partial blocks for occupancy. Writes UNNORMALIZED partial acc + rowsums.
// 256 threads, TI=64 rows, TJ=64-wide j tiles, 16 tiles per block.
//  score mapping: sr = tid>>2 (row), cols 4*(tid&3) + 16k, k=0..3
//  accum mapping: cg = tid&7 -> cols 8cg..8cg+7 ; rg = tid>>3 -> rows {rg, rg+32}
// Wh_s: 16B-chunk XOR swizzle -> 1 wf per LDS.128; p_s stride 68 -> stores 4 wf
// (minimum), loads 1 wf.
// ---------------------------------------------------------------------------
#define TI 64
#define TJ 64
#define TH 256
#define STR 68

__global__ void __launch_bounds__(TH, 3) k_attn(const float* __restrict__ adj) {
    __shared__ __align__(16) float Wh_s[TJ][STR];   // 17.4 KB
    __shared__ __align__(16) float p_s[TI][STR];    // 17.4 KB
    __shared__ float f_s[TI];
    __shared__ float rowsum[TI];

    int i0    = blockIdx.x * TI;
    int js    = blockIdx.y;
    int b     = blockIdx.z;
    int jbase = js * (N_ / JSPLIT);
    int tid   = threadIdx.x;

    int sr = tid >> 2;                 // score row
    int sq = (tid & 3) * 4;            // score col phase
    int cg = tid & 7;                  // accum col group (8 cols)
    int rg = tid >> 3;                 // accum rows {rg, rg+32}

    // swizzled 16B-chunk offsets for this thread's two w-chunks
    int oA = ((2 * cg)     ^ (((2 * cg)     >> 3) & 1)) * 4;
    int oB = ((2 * cg + 1) ^ (((2 * cg + 1) >> 3) & 1)) * 4;

    const float* Wh_b  = g_Wh + (size_t)b * N_ * FOUT;
    const float* gg    = g_g + b * N_;
    const float* adj_r = adj + (size_t)(i0 + sr) * N_ + jbase;

    if (tid < TI) {
        f_s[tid]    = g_f[b * N_ + i0 + tid];
        rowsum[tid] = 0.f;
    }
    __syncthreads();
    const float fi = f_s[sr];

    unsigned long long acc[2][4];
    #pragma unroll
    for (int r = 0; r < 2; r++)
        #pragma unroll
        for (int c = 0; c < 4; c++) acc[r][c] = 0ull;

    for (int jt = 0; jt < (N_ / JSPLIT) / TJ; jt++) {
        int j0 = jbase + jt * TJ;
        if (jt) __syncthreads();       // prev accumulate done with Wh_s / p_s

        // ---- async-copy Wh tile gmem->shared (swizzled), overlaps score ----
        #pragma unroll
        for (int l = 0; l < 4; l++) {
            int idx = tid + TH * l;            // 0..1023 16B chunks
            int row = idx >> 4, q = idx & 15;
            int qs = q ^ ((q >> 3) & 1);
            CP16(smem_u32(&Wh_s[row][qs * 4]),
                 &Wh_b[(size_t)(j0 + row) * FOUT + q * 4]);
        }

        // ---- scores: p = adj>0 ? exp(lrelu(f_i + g_j)) : 0 ----
        float part = 0.f;
        #pragma unroll
        for (int k = 0; k < 4; k++) {
            int c = sq + 16 * k;
            float4 ad = *(const float4*)&adj_r[jt * TJ + c];
            float4 gv = *(const float4*)&gg[j0 + c];
            float4 P;
            float v;
            v = fi + gv.x; v = fmaxf(v, ALPHA * v); P.x = (ad.x > 0.f) ? __expf(v) : 0.f;
            v = fi + gv.y; v = fmaxf(v, ALPHA * v); P.y = (ad.y > 0.f) ? __expf(v) : 0.f;
            v = fi + gv.z; v = fmaxf(v, ALPHA * v); P.z = (ad.z > 0.f) ? __expf(v) : 0.f;
            v = fi + gv.w; v = fmaxf(v, ALPHA * v); P.w = (ad.w > 0.f) ? __expf(v) : 0.f;
            *(float4*)&p_s[sr][c] = P;
            part += (P.x + P.y) + (P.z + P.w);
        }
        part += __shfl_xor_sync(0xffffffffu, part, 1);
        part += __shfl_xor_sync(0xffffffffu, part, 2);
        if (!(tid & 3)) rowsum[sr] += part;

        asm volatile("cp.async.wait_all;" ::: "memory");
        __syncthreads();

        // ---- accumulate: acc[r][*] += p[row_r][j] * Wh[j][cols] ----
        #pragma unroll 4
        for (int jc = 0; jc < TJ; jc += 4) {
            float4 pv0 = *(const float4*)&p_s[rg     ][jc];
            float4 pv1 = *(const float4*)&p_s[rg + 32][jc];
            const float* pa0 = (const float*)&pv0;
            const float* pa1 = (const float*)&pv1;
            #pragma unroll
            for (int jj = 0; jj < 4; jj++) {
                ulonglong2 wA = *(const ulonglong2*)&Wh_s[jc + jj][oA];
                ulonglong2 wB = *(const ulonglong2*)&Wh_s[jc + jj][oB];
                unsigned long long pd;
                pd = pack2(pa0[jj]);
                acc[0][0] = fma2(pd, wA.x, acc[0][0]);
                acc[0][1] = fma2(pd, wA.y, acc[0][1]);
                acc[0][2] = fma2(pd, wB.x, acc[0][2]);
                acc[0][3] = fma2(pd, wB.y, acc[0][3]);
                pd = pack2(pa1[jj]);
                acc[1][0] = fma2(pd, wA.x, acc[1][0]);
                acc[1][1] = fma2(pd, wA.y, acc[1][1]);
                acc[1][2] = fma2(pd, wB.x, acc[1][2]);
                acc[1][3] = fma2(pd, wB.y, acc[1][3]);
            }
        }
    }
    __syncthreads();   // all rowsum contributions landed

    float* pa = g_pacc[js] + ((size_t)b * N_ + i0) * FOUT;
    #pragma unroll
    for (int r = 0; r < 2; r++) {
        int row = rg + 32 * r;
        float2 v0 = *(float2*)&acc[r][0];
        float2 v1 = *(float2*)&acc[r][1];
        float2 v2 = *(float2*)&acc[r][2];
        float2 v3 = *(float2*)&acc[r][3];
        float4 oa = make_float4(v0.x, v0.y, v1.x, v1.y);
        float4 ob = make_float4(v2.x, v2.y, v3.x, v3.y);
        *(float4*)&pa[(size_t)row * FOUT + 8 * cg]     = oa;
        *(float4*)&pa[(size_t)row * FOUT + 8 * cg + 4] = ob;
    }
    if (tid < TI) g_psum[js][b * N_ + i0 + tid] = rowsum[tid];
}

// ---------------------------------------------------------------------------
// Kernel 3: combine partials: out = (sum_js pacc) / (sum_js psum)
// ---------------------------------------------------------------------------
__global__ void __launch_bounds__(256) k_comb(float* __restrict__ out) {
    int idx = blockIdx.x * 256 + threadIdx.x;      // float4 index
    int row = idx >> 4;                            // FOUT/4 = 16 float4 per row
    float4 a = *(const float4*)&g_pacc[0][(size_t)idx * 4];
    float4 c = *(const float4*)&g_pacc[1][(size_t)idx * 4];
    float inv = 1.0f / (g_psum[0][row] + g_psum[1][row]);
    float4 o;
    o.x = (a.x + c.x) * inv;
    o.y = (a.y + c.y) * inv;
    o.z = (a.z + c.z) * inv;
    o.w = (a.w + c.w) * inv;
    *(float4*)&out[(size_t)idx * 4] = o;
}

// ---------------------------------------------------------------------------
extern "C" void kernel_launch(void* const* d_in, const int* in_sizes, int n_in,
                              void* d_out, int out_size) {
    const float* h   = (const float*)d_in[0];
    const float* adj = (const float*)d_in[1];
    const float* W   = (const float*)d_in[2];
    const float* a   = (const float*)d_in[3];
    float* out = (float*)d_out;

    k_wh<<<(B_ * N_) / 16, 256>>>(h, W, a);

    dim3 grid(N_ / TI, JSPLIT, B_);
    k_attn<<<grid, TH>>>(adj);

    k_comb<<<(B_ * N_ * FOUT / 4) / 256, 256>>>(out);
}

// round 7
// speedup vs baseline: 1.5271x; 1.5271x over previous
#include <cuda_runtime.h>
#include <cuda_bf16.h>

#define B_     8
#define N_     2048
#define FIN    128
#define FOUT   64
#define ALPHA  0.2f
#define JSPLIT 4

// Scratch (device globals — no allocation allowed)
__device__ float g_Wh[B_ * N_ * FOUT];            // 4 MB
__device__ float g_f[B_ * N_];
__device__ float g_g[B_ * N_];
__device__ float g_pacc[JSPLIT][B_ * N_ * FOUT];  // 16 MB partial accumulators
__device__ float g_psum[JSPLIT][B_ * N_];         // partial rowsums

// ---------------------------------------------------------------------------
// packed fp32x2 helpers (sm_100+ PTX; ptxas never emits FFMA2 from C++)
// ---------------------------------------------------------------------------
__device__ __forceinline__ unsigned long long fma2(unsigned long long a,
                                                   unsigned long long b,
                                                   unsigned long long c) {
    unsigned long long d;
    asm("fma.rn.f32x2 %0, %1, %2, %3;" : "=l"(d) : "l"(a), "l"(b), "l"(c));
    return d;
}
__device__ __forceinline__ unsigned long long pack2(float p) {
    unsigned long long d;
    asm("mov.b64 %0, {%1, %1};" : "=l"(d) : "r"(__float_as_uint(p)));
    return d;
}
__device__ __forceinline__ unsigned smem_u32(const void* p) {
    return (unsigned)__cvta_generic_to_shared(p);
}
#define CP16(dst, src) \
    asm volatile("cp.async.cg.shared.global [%0], [%1], 16;" :: "r"(dst), "l"(src))

// ---------------------------------------------------------------------------
// Kernel 1: Wh = h @ W ; f = Wh @ a1 ; g = Wh @ a2
// W_t stored with per-row XOR chunk swizzle (stride 128, chunk qs=(q+fc)&31)
// -> the fc-indexed LDS.128 reads hit all 32 banks (was 8-way conflicted).
// ---------------------------------------------------------------------------
__global__ void __launch_bounds__(256) k_wh(const float* __restrict__ h,
                                            const float* __restrict__ W,
                                            const float* __restrict__ a) {
    __shared__ __align__(16) float W_t[FOUT][FIN];      // swizzled, 32 KB
    __shared__ __align__(16) float h_s[16][FIN];
    __shared__ float red[16][2][2];

    int row0 = blockIdx.x * 16;
    int tid  = threadIdx.x;
    int fc   = tid & 63;
    int rg   = tid >> 6;

    // load W transposed + swizzled
    #pragma unroll 8
    for (int l = 0; l < 32; l++) {
        int idx = tid + l * 256;
        int k = idx >> 6, c = idx & 63;
        int qs = ((k >> 2) + c) & 31;
        W_t[c][qs * 4 + (k & 3)] = W[k * FOUT + c];
    }
    #pragma unroll
    for (int l = 0; l < 8; l++) {
        int idx = tid + l * 256;
        int r = idx >> 7, k = idx & 127;
        h_s[r][k] = h[(size_t)(row0 + r) * FIN + k];
    }
    __syncthreads();

    float acc[4] = {0.f, 0.f, 0.f, 0.f};
    #pragma unroll 4
    for (int k4 = 0; k4 < FIN; k4 += 4) {
        int qs = ((k4 >> 2) + fc) & 31;
        float4 w = *(const float4*)&W_t[fc][qs * 4];
        #pragma unroll
        for (int r = 0; r < 4; r++) {
            float4 hv = *(const float4*)&h_s[rg * 4 + r][k4];
            acc[r] = fmaf(hv.x, w.x, acc[r]);
            acc[r] = fmaf(hv.y, w.y, acc[r]);
            acc[r] = fmaf(hv.z, w.z, acc[r]);
            acc[r] = fmaf(hv.w, w.w, acc[r]);
        }
    }

    float a1 = a[fc], a2 = a[FOUT + fc];
    float pf[4], pg[4];
    #pragma unroll
    for (int r = 0; r < 4; r++) {
        g_Wh[(size_t)(row0 + rg * 4 + r) * FOUT + fc] = acc[r];
        pf[r] = acc[r] * a1;
        pg[r] = acc[r] * a2;
    }
    #pragma unroll
    for (int off = 16; off > 0; off >>= 1) {
        #pragma unroll
        for (int r = 0; r < 4; r++) {
            pf[r] += __shfl_down_sync(0xffffffffu, pf[r], off);
            pg[r] += __shfl_down_sync(0xffffffffu, pg[r], off);
        }
    }
    int hb = (tid >> 5) & 1;
    if ((tid & 31) == 0) {
        #pragma unroll
        for (int r = 0; r < 4; r++) {
            red[rg * 4 + r][hb][0] = pf[r];
            red[rg * 4 + r][hb][1] = pg[r];
        }
    }
    __syncthreads();
    if (tid < 16) {
        g_f[row0 + tid] = red[tid][0][0] + red[tid][1][0];
        g_g[row0 + tid] = red[tid][0][1] + red[tid][1][1];
    }
}

// ---------------------------------------------------------------------------
// Kernel 2: fused masked-softmax attention + att@Wh, j-split into JSPLIT
// blocks (occupancy); writes UNNORMALIZED partial acc + partial rowsums.
// EXACT round-5 economical blocking: 128 threads, TI=64, TJ=64, 8 tiles/CTA.
//  score mapping: sr = tid>>1 (row), cols (tid&1)*4 + 8k, k=0..7
//  accum mapping: cg = tid&7 (8 cols), rg = tid>>3 -> rows {rg,+16,+32,+48}
// Wh_s: 16B-chunk XOR swizzle -> 1 wf per w-LDS.128; p_s stride 68 bank-clean.
// ---------------------------------------------------------------------------
#define TI 64
#define TJ 64
#define TH 128
#define STR 68

__global__ void __launch_bounds__(TH, 5) k_attn(const float* __restrict__ adj) {
    __shared__ __align__(16) float Wh_s[TJ][STR];   // 17.4 KB
    __shared__ __align__(16) float p_s[TI][STR];    // 17.4 KB
    __shared__ float f_s[TI];
    __shared__ float rowsum[TI];

    int i0    = blockIdx.x * TI;
    int js    = blockIdx.y;
    int b     = blockIdx.z;
    int jbase = js * (N_ / JSPLIT);
    int tid   = threadIdx.x;

    int sr = tid >> 1;                 // score row
    int sq = (tid & 1) * 4;            // score col phase
    int cg = tid & 7;                  // accum col group (8 cols)
    int rg = tid >> 3;                 // accum rows {rg, rg+16, rg+32, rg+48}

    int oA = ((2 * cg)     ^ (((2 * cg)     >> 3) & 1)) * 4;
    int oB = ((2 * cg + 1) ^ (((2 * cg + 1) >> 3) & 1)) * 4;

    const float* Wh_b  = g_Wh + (size_t)b * N_ * FOUT;
    const float* gg    = g_g + b * N_;
    const float* adj_r = adj + (size_t)(i0 + sr) * N_ + jbase;

    if (tid < TI) {
        f_s[tid]    = g_f[b * N_ + i0 + tid];
        rowsum[tid] = 0.f;
    }
    __syncthreads();
    const float fi = f_s[sr];

    unsigned long long acc[4][4];
    #pragma unroll
    for (int r = 0; r < 4; r++)
        #pragma unroll
        for (int c = 0; c < 4; c++) acc[r][c] = 0ull;

    for (int jt = 0; jt < (N_ / JSPLIT) / TJ; jt++) {
        int j0 = jbase + jt * TJ;
        if (jt) __syncthreads();       // prev accumulate done with Wh_s / p_s

        // ---- async-copy Wh tile gmem->shared (swizzled), overlaps score ----
        #pragma unroll
        for (int l = 0; l < 8; l++) {
            int idx = tid + TH * l;            // 0..1023 16B chunks
            int row = idx >> 4, q = idx & 15;
            int qs = q ^ ((q >> 3) & 1);
            CP16(smem_u32(&Wh_s[row][qs * 4]),
                 &Wh_b[(size_t)(j0 + row) * FOUT + q * 4]);
        }

        // ---- scores: p = adj>0 ? exp(lrelu(f_i + g_j)) : 0 ----
        float part = 0.f;
        #pragma unroll
        for (int k = 0; k < 8; k++) {
            int c = sq + 8 * k;
            float4 ad = *(const float4*)&adj_r[jt * TJ + c];
            float4 gv = *(const float4*)&gg[j0 + c];
            float4 P;
            float v;
            v = fi + gv.x; v = fmaxf(v, ALPHA * v); P.x = (ad.x > 0.f) ? __expf(v) : 0.f;
            v = fi + gv.y; v = fmaxf(v, ALPHA * v); P.y = (ad.y > 0.f) ? __expf(v) : 0.f;
            v = fi + gv.z; v = fmaxf(v, ALPHA * v); P.z = (ad.z > 0.f) ? __expf(v) : 0.f;
            v = fi + gv.w; v = fmaxf(v, ALPHA * v); P.w = (ad.w > 0.f) ? __expf(v) : 0.f;
            *(float4*)&p_s[sr][c] = P;
            part += (P.x + P.y) + (P.z + P.w);
        }
        part += __shfl_xor_sync(0xffffffffu, part, 1);
        if (!(tid & 1)) rowsum[sr] += part;

        asm volatile("cp.async.wait_all;" ::: "memory");
        __syncthreads();

        // ---- accumulate: acc[r][*] += p[row_r][j] * Wh[j][cols] ----
        #pragma unroll 2
        for (int jc = 0; jc < TJ; jc += 4) {
            float4 pv0 = *(const float4*)&p_s[rg     ][jc];
            float4 pv1 = *(const float4*)&p_s[rg + 16][jc];
            float4 pv2 = *(const float4*)&p_s[rg + 32][jc];
            float4 pv3 = *(const float4*)&p_s[rg + 48][jc];
            const float* pa0 = (const float*)&pv0;
            const float* pa1 = (const float*)&pv1;
            const float* pa2 = (const float*)&pv2;
            const float* pa3 = (const float*)&pv3;
            #pragma unroll
            for (int jj = 0; jj < 4; jj++) {
                ulonglong2 wA = *(const ulonglong2*)&Wh_s[jc + jj][oA];
                ulonglong2 wB = *(const ulonglong2*)&Wh_s[jc + jj][oB];
                unsigned long long pd;
                pd = pack2(pa0[jj]);
                acc[0][0] = fma2(pd, wA.x, acc[0][0]);
                acc[0][1] = fma2(pd, wA.y, acc[0][1]);
                acc[0][2] = fma2(pd, wB.x, acc[0][2]);
                acc[0][3] = fma2(pd, wB.y, acc[0][3]);
                pd = pack2(pa1[jj]);
                acc[1][0] = fma2(pd, wA.x, acc[1][0]);
                acc[1][1] = fma2(pd, wA.y, acc[1][1]);
                acc[1][2] = fma2(pd, wB.x, acc[1][2]);
                acc[1][3] = fma2(pd, wB.y, acc[1][3]);
                pd = pack2(pa2[jj]);
                acc[2][0] = fma2(pd, wA.x, acc[2][0]);
                acc[2][1] = fma2(pd, wA.y, acc[2][1]);
                acc[2][2] = fma2(pd, wB.x, acc[2][2]);
                acc[2][3] = fma2(pd, wB.y, acc[2][3]);
                pd = pack2(pa3[jj]);
                acc[3][0] = fma2(pd, wA.x, acc[3][0]);
                acc[3][1] = fma2(pd, wA.y, acc[3][1]);
                acc[3][2] = fma2(pd, wB.x, acc[3][2]);
                acc[3][3] = fma2(pd, wB.y, acc[3][3]);
            }
        }
    }
    __syncthreads();   // all rowsum contributions landed

    float* pa = g_pacc[js] + ((size_t)b * N_ + i0) * FOUT;
    #pragma unroll
    for (int r = 0; r < 4; r++) {
        int row = rg + 16 * r;
        float2 v0 = *(float2*)&acc[r][0];
        float2 v1 = *(float2*)&acc[r][1];
        float2 v2 = *(float2*)&acc[r][2];
        float2 v3 = *(float2*)&acc[r][3];
        float4 oa = make_float4(v0.x, v0.y, v1.x, v1.y);
        float4 ob = make_float4(v2.x, v2.y, v3.x, v3.y);
        *(float4*)&pa[(size_t)row * FOUT + 8 * cg]     = oa;
        *(float4*)&pa[(size_t)row * FOUT + 8 * cg + 4] = ob;
    }
    if (tid < TI) g_psum[js][b * N_ + i0 + tid] = rowsum[tid];
}

// ---------------------------------------------------------------------------
// Kernel 3: combine partials: out = (sum_js pacc) / (sum_js psum)
// ---------------------------------------------------------------------------
__global__ void __launch_bounds__(256) k_comb(float* __restrict__ out) {
    int idx = blockIdx.x * 256 + threadIdx.x;      // float4 index
    int row = idx >> 4;                            // 16 float4 per row
    float4 s = *(const float4*)&g_pacc[0][(size_t)idx * 4];
    float den = g_psum[0][row];
    #pragma unroll
    for (int js = 1; js < JSPLIT; js++) {
        float4 c = *(const float4*)&g_pacc[js][(size_t)idx * 4];
        s.x += c.x; s.y += c.y; s.z += c.z; s.w += c.w;
        den += g_psum[js][row];
    }
    float inv = 1.0f / den;
    float4 o = make_float4(s.x * inv, s.y * inv, s.z * inv, s.w * inv);
    *(float4*)&out[(size_t)idx * 4] = o;
}

// ---------------------------------------------------------------------------
extern "C" void kernel_launch(void* const* d_in, const int* in_sizes, int n_in,
                              void* d_out, int out_size) {
    const float* h   = (const float*)d_in[0];
    const float* adj = (const float*)d_in[1];
    const float* W   = (const float*)d_in[2];
    const float* a   = (const float*)d_in[3];
    float* out = (float*)d_out;

    k_wh<<<(B_ * N_) / 16, 256>>>(h, W, a);

    dim3 grid(N_ / TI, JSPLIT, B_);
    k_attn<<<grid, TH>>>(adj);

    k_comb<<<(B_ * N_ * FOUT / 4) / 256, 256>>>(out);
}